// round 1
// baseline (speedup 1.0000x reference)
#include <cuda_runtime.h>
#include <cuda_bf16.h>

// FAPE loss: B=4, N=2048
//   xp[b,i,j,:] = Rp[b,i]^T @ (xp_atoms[b,j] - tp[b,i])
//   xt[b,i,j,:] = Rt[b,i]^T @ (xt_atoms[b,j] - tt[b,i])
//   dist = min(sqrt(||xp-xt||^2 + 1e-4), 10)
//   out[b] = 0.1 * mean_ij dist
//
// Simplification: d = Rp^T xp_j + (-Rt^T) xt_j + dt_i,
//   dt_i = Rt^T tt_i - Rp^T tp_i
// Precompute per (b,i): [Rp^T (9), -Rt^T (9), dt (3)] -> 21 floats, padded to 24.

#define BB 4
#define NN 2048
#define NBI 8           // i-blocks per b (256 i's each)
#define NBJ 8           // j-chunks per b (256 j's each)
#define BLK 256
#define NBLOCKS (BB * NBI * NBJ)   // 256

__device__ float g_frames[BB * NN * 24];   // ~786 KB scratch
__device__ float g_partials[NBLOCKS];

__device__ __forceinline__ float fsqrt_approx(float x) {
    float y;
    asm("sqrt.approx.f32 %0, %1;" : "=f"(y) : "f"(x));
    return y;
}

__global__ void fape_prep(const float* __restrict__ pR, const float* __restrict__ pT,
                          const float* __restrict__ tR, const float* __restrict__ tT) {
    int idx = blockIdx.x * blockDim.x + threadIdx.x;   // b*NN + i
    if (idx >= BB * NN) return;
    const float* Rp = pR + idx * 9;
    const float* Rt = tR + idx * 9;
    const float tp0 = pT[idx*3+0], tp1 = pT[idx*3+1], tp2 = pT[idx*3+2];
    const float tt0 = tT[idx*3+0], tt1 = tT[idx*3+1], tt2 = tT[idx*3+2];
    float* f = g_frames + idx * 24;
#pragma unroll
    for (int o = 0; o < 3; o++) {
        float rp0 = Rp[0*3+o], rp1 = Rp[1*3+o], rp2 = Rp[2*3+o];
        float rt0 = Rt[0*3+o], rt1 = Rt[1*3+o], rt2 = Rt[2*3+o];
        f[o*3+0] = rp0;  f[o*3+1] = rp1;  f[o*3+2] = rp2;
        f[9+o*3+0] = -rt0; f[9+o*3+1] = -rt1; f[9+o*3+2] = -rt2;
        // dt_o = -(Rp^T tp)_o + (Rt^T tt)_o
        f[18+o] = (rt0*tt0 + rt1*tt1 + rt2*tt2) - (rp0*tp0 + rp1*tp1 + rp2*tp2);
    }
    f[21] = 0.f; f[22] = 0.f; f[23] = 0.f;
}

__global__ void __launch_bounds__(BLK)
fape_main(const float* __restrict__ pX, const float* __restrict__ tX) {
    __shared__ float sj[BLK * 8];      // per j: xp0,xp1,xp2,xt0,xt1,xt2,pad,pad
    __shared__ float red[BLK];

    const int bid = blockIdx.x;
    const int b  = bid >> 6;           // / (NBI*NBJ)
    const int rem = bid & 63;
    const int ib = rem >> 3;
    const int jb = rem & 7;
    const int t  = threadIdx.x;

    // Load this block's j-chunk of atom positions into shared.
    {
        int j = jb * BLK + t;
        const float* xp = pX + (b * NN + j) * 3;
        const float* xt = tX + (b * NN + j) * 3;
        float* s = sj + t * 8;
        s[0] = xp[0]; s[1] = xp[1]; s[2] = xp[2];
        s[3] = xt[0]; s[4] = xt[1]; s[5] = xt[2];
        s[6] = 0.f;   s[7] = 0.f;
    }
    __syncthreads();

    // Each thread owns one i. Load its 21-float frame via float4s.
    const int i = ib * BLK + t;
    const float* f = g_frames + (b * NN + i) * 24;
    const float4 v0 = *(const float4*)(f + 0);
    const float4 v1 = *(const float4*)(f + 4);
    const float4 v2 = *(const float4*)(f + 8);
    const float4 v3 = *(const float4*)(f + 12);
    const float4 v4 = *(const float4*)(f + 16);
    const float4 v5 = *(const float4*)(f + 20);
    // Rp^T rows (o-major): Rp[o*3+k]
    const float p00=v0.x, p01=v0.y, p02=v0.z;
    const float p10=v0.w, p11=v1.x, p12=v1.y;
    const float p20=v1.z, p21=v1.w, p22=v2.x;
    // -Rt^T rows
    const float q00=v2.y, q01=v2.z, q02=v2.w;
    const float q10=v3.x, q11=v3.y, q12=v3.z;
    const float q20=v3.w, q21=v4.x, q22=v4.y;
    const float dt0=v4.z, dt1=v4.w, dt2=v5.x;

    float acc = 0.f;
#pragma unroll 4
    for (int j = 0; j < BLK; j++) {
        const float* s = sj + j * 8;
        // warp-uniform address -> broadcast LDS (conflict-free)
        const float4 a = *(const float4*)(s);       // xp0,xp1,xp2,xt0
        const float4 c = *(const float4*)(s + 4);   // xt1,xt2,pad,pad

        float d0 = fmaf(p00, a.x, fmaf(p01, a.y, fmaf(p02, a.z, dt0)));
        d0 = fmaf(q00, a.w, fmaf(q01, c.x, fmaf(q02, c.y, d0)));
        float d1 = fmaf(p10, a.x, fmaf(p11, a.y, fmaf(p12, a.z, dt1)));
        d1 = fmaf(q10, a.w, fmaf(q11, c.x, fmaf(q12, c.y, d1)));
        float d2 = fmaf(p20, a.x, fmaf(p21, a.y, fmaf(p22, a.z, dt2)));
        d2 = fmaf(q20, a.w, fmaf(q21, c.x, fmaf(q22, c.y, d2)));

        float s2 = fmaf(d0, d0, fmaf(d1, d1, fmaf(d2, d2, 1e-4f)));
        s2 = fminf(s2, 100.0f);      // min(sqrt(x),10) == sqrt(min(x,100))
        acc += fsqrt_approx(s2);
    }

    // Deterministic block tree reduction.
    red[t] = acc;
    __syncthreads();
#pragma unroll
    for (int stride = BLK / 2; stride >= 1; stride >>= 1) {
        if (t < stride) red[t] += red[t + stride];
        __syncthreads();
    }
    if (t == 0) g_partials[bid] = red[0];
}

__global__ void fape_finalize(float* __restrict__ out) {
    int b = threadIdx.x;
    if (b < BB) {
        float s = 0.f;
        for (int k = 0; k < NBI * NBJ; k++)
            s += g_partials[b * (NBI * NBJ) + k];
        out[b] = s * (1.0f / (10.0f * (float)NN * (float)NN));
    }
}

extern "C" void kernel_launch(void* const* d_in, const int* in_sizes, int n_in,
                              void* d_out, int out_size) {
    const float* pR = (const float*)d_in[0];  // predicted_rotations   [B,N,3,3]
    const float* pT = (const float*)d_in[1];  // predicted_translations[B,N,3]
    const float* pX = (const float*)d_in[2];  // predicted_atom_positions
    const float* tR = (const float*)d_in[3];  // true_rotations
    const float* tT = (const float*)d_in[4];  // true_translations
    const float* tX = (const float*)d_in[5];  // true_atom_positions

    fape_prep<<<(BB * NN + 255) / 256, 256>>>(pR, pT, tR, tT);
    fape_main<<<NBLOCKS, BLK>>>(pX, tX);
    fape_finalize<<<1, 32>>>((float*)d_out);
}

// round 2
// speedup vs baseline: 1.8955x; 1.8955x over previous
#include <cuda_runtime.h>
#include <cuda_bf16.h>

// FAPE loss, fused single kernel. B=4, N=2048.
//   d(i,j) = Rp_i^T xp_j + (-Rt_i^T) xt_j + dt_i,  dt_i = Rt_i^T tt_i - Rp_i^T tp_i
//   out[b] = 0.1 * mean_ij min(sqrt(||d||^2 + 1e-4), 10)
//
// Inner loop processes TWO j's per iteration with packed fma.rn.f32x2 (FFMA2),
// halving fma-pipe instruction count. Shared j-data is SoA so LDS.64 loads a
// pre-packed {y_j, y_j+1}. Frames are recomputed per block (no scratch pass).
// Final reduction: last-block-done counter, fixed-order sum (deterministic).

#define BB 4
#define NN 2048
#define NBI 8
#define NBJ 8
#define BLK 256
#define NBLOCKS (BB * NBI * NBJ)   // 256

__device__ float g_partials[NBLOCKS];
__device__ unsigned int g_count = 0;

typedef unsigned long long u64;

__device__ __forceinline__ u64 pack2(float x, float y) {
    u64 r; asm("mov.b64 %0, {%1,%2};" : "=l"(r) : "f"(x), "f"(y)); return r;
}
__device__ __forceinline__ void unpack2(u64 v, float& x, float& y) {
    asm("mov.b64 {%0,%1}, %2;" : "=f"(x), "=f"(y) : "l"(v));
}
__device__ __forceinline__ u64 ffma2(u64 a, u64 b, u64 c) {
    u64 d; asm("fma.rn.f32x2 %0, %1, %2, %3;" : "=l"(d) : "l"(a), "l"(b), "l"(c)); return d;
}
__device__ __forceinline__ float fsqrt_approx(float x) {
    float y; asm("sqrt.approx.f32 %0, %1;" : "=f"(y) : "f"(x)); return y;
}

__global__ void __launch_bounds__(BLK)
fape_fused(const float* __restrict__ pR, const float* __restrict__ pT,
           const float* __restrict__ pX, const float* __restrict__ tR,
           const float* __restrict__ tT, const float* __restrict__ tX,
           float* __restrict__ out) {
    __shared__ __align__(16) float sy[6][BLK];   // SoA: xp0,xp1,xp2,xt0,xt1,xt2
    __shared__ float red[BLK];

    const int bid = blockIdx.x;
    const int b  = bid >> 6;
    const int ib = (bid >> 3) & 7;
    const int jb = bid & 7;
    const int t  = threadIdx.x;

    // Stage this block's j-chunk of atom positions into shared (SoA).
    {
        const int j = jb * BLK + t;
        const float* xp = pX + (b * NN + j) * 3;
        const float* xt = tX + (b * NN + j) * 3;
        sy[0][t] = xp[0]; sy[1][t] = xp[1]; sy[2][t] = xp[2];
        sy[3][t] = xt[0]; sy[4][t] = xt[1]; sy[5][t] = xt[2];
    }

    // Compute this thread's i-frame directly (fused prep), pre-packed {v,v}.
    u64 P[9], Q[9], DT[3];
    {
        const int idx = b * NN + ib * BLK + t;
        const float* Rp = pR + idx * 9;
        const float* Rt = tR + idx * 9;
        const float tp0 = pT[idx*3+0], tp1 = pT[idx*3+1], tp2 = pT[idx*3+2];
        const float tt0 = tT[idx*3+0], tt1 = tT[idx*3+1], tt2 = tT[idx*3+2];
#pragma unroll
        for (int o = 0; o < 3; o++) {
            const float rp0 = Rp[0*3+o], rp1 = Rp[1*3+o], rp2 = Rp[2*3+o];
            const float rt0 = Rt[0*3+o], rt1 = Rt[1*3+o], rt2 = Rt[2*3+o];
            P[o*3+0] = pack2(rp0, rp0);
            P[o*3+1] = pack2(rp1, rp1);
            P[o*3+2] = pack2(rp2, rp2);
            Q[o*3+0] = pack2(-rt0, -rt0);
            Q[o*3+1] = pack2(-rt1, -rt1);
            Q[o*3+2] = pack2(-rt2, -rt2);
            const float dt = (rt0*tt0 + rt1*tt1 + rt2*tt2)
                           - (rp0*tp0 + rp1*tp1 + rp2*tp2);
            DT[o] = pack2(dt, dt);
        }
    }
    const u64 EPS2 = pack2(1e-4f, 1e-4f);
    __syncthreads();

    float acc0 = 0.f, acc1 = 0.f;
#pragma unroll 4
    for (int j = 0; j < BLK; j += 2) {
        // Warp-uniform LDS.64: packed pair {y_j, y_{j+1}} per component.
        const u64 y0 = *(const u64*)&sy[0][j];
        const u64 y1 = *(const u64*)&sy[1][j];
        const u64 y2 = *(const u64*)&sy[2][j];
        const u64 y3 = *(const u64*)&sy[3][j];
        const u64 y4 = *(const u64*)&sy[4][j];
        const u64 y5 = *(const u64*)&sy[5][j];

        u64 d0 = ffma2(P[0], y0, ffma2(P[1], y1, ffma2(P[2], y2,
                 ffma2(Q[0], y3, ffma2(Q[1], y4, ffma2(Q[2], y5, DT[0]))))));
        u64 d1 = ffma2(P[3], y0, ffma2(P[4], y1, ffma2(P[5], y2,
                 ffma2(Q[3], y3, ffma2(Q[4], y4, ffma2(Q[5], y5, DT[1]))))));
        u64 d2 = ffma2(P[6], y0, ffma2(P[7], y1, ffma2(P[8], y2,
                 ffma2(Q[6], y3, ffma2(Q[7], y4, ffma2(Q[8], y5, DT[2]))))));

        u64 s2 = ffma2(d0, d0, ffma2(d1, d1, ffma2(d2, d2, EPS2)));
        float lo, hi;
        unpack2(s2, lo, hi);
        // min(sqrt(x+eps), 10) == sqrt(min(x+eps, 100))
        acc0 += fsqrt_approx(fminf(lo, 100.0f));
        acc1 += fsqrt_approx(fminf(hi, 100.0f));
    }

    // Deterministic block tree reduction.
    red[t] = acc0 + acc1;
    __syncthreads();
#pragma unroll
    for (int stride = BLK / 2; stride >= 1; stride >>= 1) {
        if (t < stride) red[t] += red[t + stride];
        __syncthreads();
    }

    if (t == 0) {
        g_partials[bid] = red[0];
        __threadfence();
        const unsigned r = atomicAdd(&g_count, 1);
        if (r == NBLOCKS - 1) {
            // Last block: fixed-order final sum (deterministic).
#pragma unroll
            for (int bb = 0; bb < BB; bb++) {
                float s = 0.f;
                for (int k = 0; k < NBI * NBJ; k++)
                    s += __ldcg(&g_partials[bb * (NBI * NBJ) + k]);
                out[bb] = s * (1.0f / (10.0f * (float)NN * (float)NN));
            }
            g_count = 0;   // reset for next graph replay
        }
    }
}

extern "C" void kernel_launch(void* const* d_in, const int* in_sizes, int n_in,
                              void* d_out, int out_size) {
    const float* pR = (const float*)d_in[0];  // predicted_rotations   [B,N,3,3]
    const float* pT = (const float*)d_in[1];  // predicted_translations[B,N,3]
    const float* pX = (const float*)d_in[2];  // predicted_atom_positions
    const float* tR = (const float*)d_in[3];  // true_rotations
    const float* tT = (const float*)d_in[4];  // true_translations
    const float* tX = (const float*)d_in[5];  // true_atom_positions

    fape_fused<<<NBLOCKS, BLK>>>(pR, pT, pX, tR, tT, tX, (float*)d_out);
}